// round 14
// baseline (speedup 1.0000x reference)
#include <cuda_runtime.h>
#include <cstdint>

#define NBLK   592       // 148 SMs x 4 blocks/SM -> one wave
#define TPB    256
#define NBINS  15
#define NCOL   45        // 15 counts, 15 conf sums, 15 acc sums
#define PAD    16
#define TROWS  64        // rows per tile (8 warps x 8 rows)
#define TBYTES (TROWS * 400)   // 25600 bytes per tile
#define STAGES 2
#define SMEM_DYN (STAGES * TBYTES + 16)   // buffers + 2 mbarriers

__device__ double g_red[NCOL * PAD];
__device__ unsigned int g_ticket;

__device__ __forceinline__ float ex2f(float x) {
    float r; asm("ex2.approx.f32 %0, %1;" : "=f"(r) : "f"(x)); return r;
}
__device__ __forceinline__ uint32_t smem_u32(const void* p) {
    uint32_t a;
    asm("{ .reg .u64 t; cvta.to.shared.u64 t, %1; cvt.u32.u64 %0, t; }"
        : "=r"(a) : "l"(p));
    return a;
}
__device__ __forceinline__ void mbar_init(uint32_t a, uint32_t cnt) {
    asm volatile("mbarrier.init.shared.b64 [%0], %1;" :: "r"(a), "r"(cnt) : "memory");
}
__device__ __forceinline__ void mbar_expect_tx(uint32_t a, uint32_t bytes) {
    asm volatile("mbarrier.arrive.expect_tx.shared.b64 _, [%0], %1;"
                 :: "r"(a), "r"(bytes) : "memory");
}
__device__ __forceinline__ void bulk_g2s(uint32_t dst, const void* src,
                                         uint32_t bytes, uint32_t mbar) {
    asm volatile(
        "cp.async.bulk.shared::cta.global.mbarrier::complete_tx::bytes [%0], [%1], %2, [%3];"
        :: "r"(dst), "l"(src), "r"(bytes), "r"(mbar) : "memory");
}
__device__ __forceinline__ void mbar_wait(uint32_t a, uint32_t parity) {
    asm volatile(
        "{\n\t.reg .pred P;\n\t"
        "WL_%=:\n\t"
        "mbarrier.try_wait.parity.acquire.cta.shared::cta.b64 P, [%0], %1, 0x989680;\n\t"
        "@P bra.uni WD_%=;\n\t"
        "bra.uni WL_%=;\n\t"
        "WD_%=:\n\t}"
        :: "r"(a), "r"(parity) : "memory");
}

// Final ECE from the 15 bins, executed by the last-arriving block.
__device__ __noinline__ void finalize_ece(float* out, double n, int tid)
{
    __threadfence();
    double e = 0.0;
    if (tid < 32) {
        if (tid < NBINS) {
            const double c  = g_red[tid * PAD];
            const double cs = g_red[(NBINS + tid) * PAD];
            const double as = g_red[(2 * NBINS + tid) * PAD];
            if (c > 0.0) {
                const double d = (c > 1.0) ? c : 1.0;
                e = fabs(cs / d - as / d) * (c / n);
            }
        }
#pragma unroll
        for (int o = 16; o > 0; o >>= 1)
            e += __shfl_xor_sync(0xffffffffu, e, o);
    }
    __syncthreads();
    for (int i = tid; i < NCOL * PAD; i += TPB)
        g_red[i] = 0.0;
    if (tid == 0) {
        g_ticket = 0;
        out[0] = (float)e;
    }
}

// ---------------------------------------------------------------------------
// TMA-pipelined main pass, C=100, requires N % 64 == 0.
// Block streams 64-row tiles through a 2-stage SMEM ring via cp.async.bulk.
// Warp w computes tile rows [w*8, w*8+8), 4 lanes per row (q = lane&3).
// ---------------------------------------------------------------------------
__global__ __launch_bounds__(TPB, 4)
void ece_tma_c100(const float* __restrict__ logits,
                  const int*   __restrict__ labels,
                  int N, float* __restrict__ out, double nAll)
{
    extern __shared__ char dsm[];
    const uint32_t sbase = smem_u32(dsm);
    const uint32_t mbar0 = sbase + STAGES * TBYTES;   // full[0] @ +0, full[1] @ +8

    const int tid  = threadIdx.x;
    const int lane = tid & 31;
    const int q    = lane & 3;
    const int grp  = lane >> 2;
    const int w    = tid >> 5;
    const int ntiles = N >> 6;

    if (tid == 0) {
        mbar_init(mbar0,     1);
        mbar_init(mbar0 + 8, 1);
    }
    __syncthreads();

    // Prologue: issue first STAGES tile copies.
    if (tid == 0) {
#pragma unroll
        for (int j = 0; j < STAGES; j++) {
            const int g = blockIdx.x + j * NBLK;
            if (g < ntiles) {
                mbar_expect_tx(mbar0 + 8u * j, TBYTES);
                bulk_g2s(sbase + j * TBYTES, logits + (size_t)g * (TROWS * 100),
                         TBYTES, mbar0 + 8u * j);
            }
        }
    }

    const float L2E = 1.4426950408889634f;
    float cnt[4]  = {0.f, 0.f, 0.f, 0.f};
    float csum[4] = {0.f, 0.f, 0.f, 0.f};
    float asum[4] = {0.f, 0.f, 0.f, 0.f};

    const int tilerow = w * 8 + grp;        // this lane-group's row within a tile

    int j = 0;
#pragma unroll 1
    for (int g = blockIdx.x; g < ntiles; g += NBLK, j++) {
        const int s  = j & 1;
        const int ph = (j >> 1) & 1;

        // Label LDG issued before the wait — latency hidden behind the copy.
        const int grow = (g << 6) + tilerow;
        const int lab  = labels[grow];

        mbar_wait(mbar0 + 8u * s, (uint32_t)ph);

        const char*  rb  = dsm + s * TBYTES + tilerow * 400;
        const float* rp  = (const float*)rb;
        const float4* rp4 = (const float4*)rb;

        float4 a0 = rp4[q];      float4 a1 = rp4[q + 4];
        float4 a2 = rp4[q + 8];  float4 a3 = rp4[q + 12];
        float4 a4 = rp4[q + 16]; float4 a5 = rp4[q + 20];
        float  tl = rp[96 + q];
        const float labval = rp[lab];

        // ---- row max ----
        float m0 = fmaxf(fmaxf(a0.x, a0.y), fmaxf(a0.z, a0.w));
        float m1 = fmaxf(fmaxf(a1.x, a1.y), fmaxf(a1.z, a1.w));
        float m2 = fmaxf(fmaxf(a2.x, a2.y), fmaxf(a2.z, a2.w));
        float m3 = fmaxf(fmaxf(a3.x, a3.y), fmaxf(a3.z, a3.w));
        float m4 = fmaxf(fmaxf(a4.x, a4.y), fmaxf(a4.z, a4.w));
        float m5 = fmaxf(fmaxf(a5.x, a5.y), fmaxf(a5.z, a5.w));
        float m  = fmaxf(fmaxf(fmaxf(m0, m1), fmaxf(m2, m3)),
                         fmaxf(fmaxf(m4, m5), tl));
        m = fmaxf(m, __shfl_xor_sync(0xffffffffu, m, 1));
        m = fmaxf(m, __shfl_xor_sync(0xffffffffu, m, 2));

        // ---- sum exp(v - m) ----
        const float mb = m * L2E;
#define E(v) ex2f(fmaf((v), L2E, -mb))
        float s0 = (E(a0.x) + E(a0.y)) + (E(a0.z) + E(a0.w));
        float s1 = (E(a1.x) + E(a1.y)) + (E(a1.z) + E(a1.w));
        float s2 = (E(a2.x) + E(a2.y)) + (E(a2.z) + E(a2.w));
        float s3 = (E(a3.x) + E(a3.y)) + (E(a3.z) + E(a3.w));
        float s4 = (E(a4.x) + E(a4.y)) + (E(a4.z) + E(a4.w));
        float s5 = (E(a5.x) + E(a5.y)) + (E(a5.z) + E(a5.w));
        float ssum = ((s0 + s1) + (s2 + s3)) + ((s4 + s5) + E(tl));
#undef E
        ssum += __shfl_xor_sync(0xffffffffu, ssum, 1);
        ssum += __shfl_xor_sync(0xffffffffu, ssum, 2);

        const float conf = 1.0f / ssum;
        const float accv = (labval == m) ? 1.0f : 0.0f;
        int bin = (int)(conf * 15.0f);
        bin = min(bin, NBINS - 1);

        const bool mine = ((bin & 3) == q);
        const int  slot = bin >> 2;
#pragma unroll
        for (int ss = 0; ss < 4; ss++) {
            if (mine && slot == ss) {
                cnt[ss]  += 1.0f;
                csum[ss] += conf;
                asum[ss] += accv;
            }
        }

        // ---- stage drained; reissue it for tile j+STAGES ----
        __syncthreads();
        if (tid == 0) {
            const int gn = g + STAGES * NBLK;
            if (gn < ntiles) {
                mbar_expect_tx(mbar0 + 8u * s, TBYTES);
                bulk_g2s(sbase + s * TBYTES, logits + (size_t)gn * (TROWS * 100),
                         TBYTES, mbar0 + 8u * s);
            }
        }
    }

    // ---- combine the 8 groups within the warp ----
#pragma unroll
    for (int ss = 0; ss < 4; ss++) {
#pragma unroll
        for (int d = 4; d < 32; d <<= 1) {
            cnt[ss]  += __shfl_xor_sync(0xffffffffu, cnt[ss],  d);
            csum[ss] += __shfl_xor_sync(0xffffffffu, csum[ss], d);
            asum[ss] += __shfl_xor_sync(0xffffffffu, asum[ss], d);
        }
    }

    // ---- combine warps within the block, one atomic round per block ----
    __shared__ float sh[NCOL];
    __shared__ bool  sLast;
    if (tid < NCOL) sh[tid] = 0.0f;
    __syncthreads();
    if (lane < 4) {
#pragma unroll
        for (int ss = 0; ss < 4; ss++) {
            const int bin = q + 4 * ss;
            if (bin < NBINS) {
                atomicAdd(&sh[bin],             cnt[ss]);
                atomicAdd(&sh[NBINS + bin],     csum[ss]);
                atomicAdd(&sh[2 * NBINS + bin], asum[ss]);
            }
        }
    }
    __syncthreads();
    if (tid < NCOL)
        atomicAdd(&g_red[tid * PAD], (double)sh[tid]);

    __threadfence();
    if (tid == 0)
        sLast = (atomicAdd(&g_ticket, 1u) == (unsigned)(gridDim.x - 1));
    __syncthreads();
    if (sLast)
        finalize_ece(out, nAll, tid);
}

// ---------------------------------------------------------------------------
// Generic fallback (any C, any N): warp per row, fused finalization.
// ---------------------------------------------------------------------------
__global__ __launch_bounds__(TPB)
void ece_pass1_generic(const float* __restrict__ logits,
                       const int*   __restrict__ labels,
                       int N, int C, float* __restrict__ out, double nAll)
{
    const int tid  = threadIdx.x;
    const int lane = tid & 31;
    const int warpId = blockIdx.x * (TPB / 32) + (tid >> 5);
    const int nWarps = NBLK * (TPB / 32);
    const float L2E = 1.4426950408889634f;

    __shared__ float sh[NCOL];
    __shared__ bool  sLast;
    if (tid < NCOL) sh[tid] = 0.0f;
    __syncthreads();

    for (int row = warpId; row < N; row += nWarps) {
        const float* rp = logits + (size_t)row * C;
        float m = -3.4e38f;
        int am = 0x7fffffff;
        for (int jj = lane; jj < C; jj += 32) {
            float v = rp[jj];
            if (v > m) { m = v; am = jj; }
        }
#pragma unroll
        for (int d = 1; d < 32; d <<= 1) {
            float om = __shfl_xor_sync(0xffffffffu, m, d);
            int   oa = __shfl_xor_sync(0xffffffffu, am, d);
            if (om > m || (om == m && oa < am)) { m = om; am = oa; }
        }
        const float mb = m * L2E;
        float s = 0.f;
        for (int jj = lane; jj < C; jj += 32)
            s += ex2f(fmaf(rp[jj], L2E, -mb));
#pragma unroll
        for (int d = 1; d < 32; d <<= 1)
            s += __shfl_xor_sync(0xffffffffu, s, d);

        if (lane == 0) {
            const float conf = 1.0f / s;
            const float accv = (am == labels[row]) ? 1.0f : 0.0f;
            int bin = (int)(conf * 15.0f);
            bin = min(bin, NBINS - 1);
            atomicAdd(&sh[bin],             1.0f);
            atomicAdd(&sh[NBINS + bin],     conf);
            atomicAdd(&sh[2 * NBINS + bin], accv);
        }
    }
    __syncthreads();
    if (tid < NCOL)
        atomicAdd(&g_red[tid * PAD], (double)sh[tid]);

    __threadfence();
    if (tid == 0)
        sLast = (atomicAdd(&g_ticket, 1u) == (unsigned)(gridDim.x - 1));
    __syncthreads();
    if (sLast)
        finalize_ece(out, nAll, tid);
}

extern "C" void kernel_launch(void* const* d_in, const int* in_sizes, int n_in,
                              void* d_out, int out_size)
{
    const float* logits = (const float*)d_in[0];
    const int*   labels = (const int*)d_in[1];
    const long long total = (long long)in_sizes[0];
    const int N = in_sizes[1];
    const int C = (int)(total / N);

    if (C == 100 && (N & 63) == 0) {
        // Raise dynamic smem cap. Harmless if repeated; attribute persists from
        // the first (pre-capture) call, so a capture-time failure is ignorable.
        (void)cudaFuncSetAttribute(ece_tma_c100,
                                   cudaFuncAttributeMaxDynamicSharedMemorySize,
                                   SMEM_DYN);
        ece_tma_c100<<<NBLK, TPB, SMEM_DYN>>>(logits, labels, N,
                                              (float*)d_out, (double)N);
    } else {
        ece_pass1_generic<<<NBLK, TPB>>>(logits, labels, N, C,
                                         (float*)d_out, (double)N);
    }
}